// round 7
// baseline (speedup 1.0000x reference)
#include <cuda_runtime.h>

#define NN 50000
#define NE 10000
#define D  128
#define NNZ_INC 400000
#define NNZ_E   80000
#define NNZ_V   400000

// ---------------- scratch (device globals; no allocation allowed) ----------------
__device__ __align__(128) float g_Tv[NE * D];    // sum invDV[s]*vfeat[s] per edge
__device__ __align__(128) float g_Q[NE * D];     // efeat @ W1e.T
__device__ __align__(128) float g_Q2[NE * D];    // efeat @ W2e.T
__device__ __align__(128) float g_S1[NE];        // sum invDV[s] per edge
__device__ __align__(128) float g_cnt[NE];       // incidence count per edge
__device__ __align__(128) float g_A[NE * D];     // pre-spmm A
__device__ __align__(128) float g_ef1[NE * D];   // _efeat = efeat + emat@A
__device__ __align__(128) float g_T2[NE * D];    // sum vout[s] per edge
__device__ __align__(128) float g_ef2[NE * D];   // sum _vfeat2m[s] per edge
__device__ __align__(128) float g_M[NE * D];     // _efeat2 + B
__device__ __align__(128) float g_vf[NN * D];    // _vfeat
__device__ __align__(128) float g_vf2[NN * D];   // _vfeat2 (pre-spmm)
__device__ __align__(128) float g_vf2m[NN * D];  // vmat @ _vfeat2

__device__ __forceinline__ void red4(float* p, float a, float b, float c, float d) {
    asm volatile("red.global.add.v4.f32 [%0], {%1,%2,%3,%4};"
                 :: "l"(p), "f"(a), "f"(b), "f"(c), "f"(d) : "memory");
}

// ---------------- init: zero scratch, seed _efeat with efeat ----------------
__global__ void init_kernel(const float* __restrict__ efeat) {
    unsigned t = blockIdx.x * 256u + threadIdx.x;
    if (t < (unsigned)(NN * D)) { g_vf[t] = 0.f; g_vf2[t] = 0.f; g_vf2m[t] = 0.f; }
    if (t < (unsigned)(NE * D)) {
        g_Tv[t] = 0.f; g_T2[t] = 0.f; g_ef2[t] = 0.f;
        g_ef1[t] = efeat[t];
    }
    if (t < (unsigned)NE) { g_S1[t] = 0.f; g_cnt[t] = 0.f; }
}

// ---------------- incidence pass 1 (fused): Tv,S1,cnt scatter + _vfeat2 scatter ----
__global__ void pass1_kernel(const int* __restrict__ src, const int* __restrict__ dst,
                             const float* __restrict__ vfeat, const float* __restrict__ efeat,
                             const float* __restrict__ invDV) {
    int i = (blockIdx.x * blockDim.x + threadIdx.x) >> 5;
    if (i >= NNZ_INC) return;
    int lane = threadIdx.x & 31;
    int s = src[i], e = dst[i];
    float w = invDV[s];
    float4 v = reinterpret_cast<const float4*>(vfeat + (size_t)s * D)[lane];
    red4(g_Tv + (size_t)e * D + lane * 4, w * v.x, w * v.y, w * v.z, w * v.w);
    float4 f = reinterpret_cast<const float4*>(efeat + (size_t)e * D)[lane];
    red4(g_vf2 + (size_t)s * D + lane * 4, f.x, f.y, f.z, f.w);
    if (lane == 0) { atomicAdd(g_S1 + e, w); atomicAdd(g_cnt + e, 1.0f); }
}

// ---------------- incidence pass 2: _vfeat[s] += _efeat[e] ----------------
__global__ void pass2_kernel(const int* __restrict__ src, const int* __restrict__ dst) {
    int i = (blockIdx.x * blockDim.x + threadIdx.x) >> 5;
    if (i >= NNZ_INC) return;
    int lane = threadIdx.x & 31;
    int s = src[i], e = dst[i];
    float4 f = reinterpret_cast<const float4*>(g_ef1 + (size_t)e * D)[lane];
    red4(g_vf + (size_t)s * D + lane * 4, f.x, f.y, f.z, f.w);
}

// ---------------- incidence pass 3 (fused): T2[e]+=vout[s]; ef2[e]+=vf2m[s] -------
__global__ void pass3_kernel(const int* __restrict__ src, const int* __restrict__ dst,
                             const float* __restrict__ vout) {
    int i = (blockIdx.x * blockDim.x + threadIdx.x) >> 5;
    if (i >= NNZ_INC) return;
    int lane = threadIdx.x & 31;
    int s = src[i], e = dst[i];
    float4 a = reinterpret_cast<const float4*>(vout + (size_t)s * D)[lane];
    red4(g_T2 + (size_t)e * D + lane * 4, a.x, a.y, a.z, a.w);
    float4 b = reinterpret_cast<const float4*>(g_vf2m + (size_t)s * D)[lane];
    red4(g_ef2 + (size_t)e * D + lane * 4, b.x, b.y, b.z, b.w);
}

// ---------------- COO SpMM: Y[r] += val * X[c] (128-wide rows) ----------------
__device__ __forceinline__ void spmm_body(const int* __restrict__ rows, const int* __restrict__ cols,
                                          const float* __restrict__ vals,
                                          const float* __restrict__ X, float* __restrict__ Y, int nnz) {
    int i = (blockIdx.x * blockDim.x + threadIdx.x) >> 5;
    if (i >= nnz) return;
    int lane = threadIdx.x & 31;
    int r = rows[i], c = cols[i];
    float v = vals[i];
    float4 x = reinterpret_cast<const float4*>(X + (size_t)c * D)[lane];
    red4(Y + (size_t)r * D + lane * 4, v * x.x, v * x.y, v * x.z, v * x.w);
}

__global__ void spmm_e_kernel(const int* r, const int* c, const float* v) {
    spmm_body(r, c, v, g_A, g_ef1, NNZ_E);
}
__global__ void spmm_v_kernel(const int* r, const int* c, const float* v) {
    spmm_body(r, c, v, g_vf2, g_vf2m, NNZ_V);
}

// ---------------- GEMM: Y = X[rows,128] @ W.T (+ epilogue) ----------------
// W row-major [128, ldw], use columns [koff, koff+128).
// MODE 0: plain     MODE 2: relu
// MODE 1: Y = acc + (P1[r]+bias)*sc1[r]
// MODE 3: Y = addm[r] + sc2[r]*(acc + sc1[r]*(P1[r]+bias))
// NOTE: ws row stride MUST be a multiple of 4 floats — we read ws rows with
// LDS.128 at &ws[kk][lane*4]; a stride of 129 put odd rows at byte offset
// 516*kk (516 % 16 = 4) -> misaligned-address trap. 132 keeps 16B alignment.
template <int MODE>
__device__ __forceinline__ void gemm_body(const float* __restrict__ X, const float* __restrict__ W,
                                          int ldw, int koff, float* __restrict__ Y, int rows,
                                          const float* __restrict__ P1, const float* __restrict__ sc1,
                                          const float* __restrict__ sc2, const float* __restrict__ bias,
                                          const float* __restrict__ addm) {
    __shared__ float xs[32][128];
    __shared__ __align__(16) float ws[32][132];
    int r0 = blockIdx.x * 32;
    int tid = threadIdx.x;

    for (int idx = tid; idx < 32 * 128; idx += 256) {
        int r = idx >> 7, k = idx & 127;
        int rr = r0 + r;
        xs[r][k] = (rr < rows) ? X[(size_t)rr * 128 + k] : 0.f;
    }

    int lane = tid & 31;
    int rloc = (tid >> 5) * 4;   // warp w owns rows 4w..4w+3
    int o4 = lane * 4;
    float acc[4][4];
#pragma unroll
    for (int i = 0; i < 4; i++)
#pragma unroll
        for (int j = 0; j < 4; j++) acc[i][j] = 0.f;

    for (int kt = 0; kt < 128; kt += 32) {
        __syncthreads();
        for (int idx = tid; idx < 32 * 128; idx += 256) {
            int o = idx >> 5, kk = idx & 31;
            ws[kk][o] = W[(size_t)o * ldw + koff + kt + kk];
        }
        __syncthreads();
#pragma unroll
        for (int kk = 0; kk < 32; kk++) {
            float4 wv = *reinterpret_cast<const float4*>(&ws[kk][o4]);
#pragma unroll
            for (int i = 0; i < 4; i++) {
                float xv = xs[rloc + i][kt + kk];
                acc[i][0] += xv * wv.x;
                acc[i][1] += xv * wv.y;
                acc[i][2] += xv * wv.z;
                acc[i][3] += xv * wv.w;
            }
        }
    }

#pragma unroll
    for (int i = 0; i < 4; i++) {
        int rr = r0 + rloc + i;
        if (rr >= rows) continue;
        float4 res = make_float4(acc[i][0], acc[i][1], acc[i][2], acc[i][3]);
        if (MODE == 1) {
            float s = sc1[rr];
            float4 q = *reinterpret_cast<const float4*>(P1 + (size_t)rr * 128 + o4);
            float4 b = *reinterpret_cast<const float4*>(bias + o4);
            res.x += (q.x + b.x) * s;
            res.y += (q.y + b.y) * s;
            res.z += (q.z + b.z) * s;
            res.w += (q.w + b.w) * s;
        } else if (MODE == 2) {
            res.x = fmaxf(res.x, 0.f); res.y = fmaxf(res.y, 0.f);
            res.z = fmaxf(res.z, 0.f); res.w = fmaxf(res.w, 0.f);
        } else if (MODE == 3) {
            float c = sc1[rr];
            float id = sc2[rr];
            float4 q = *reinterpret_cast<const float4*>(P1 + (size_t)rr * 128 + o4);
            float4 b = *reinterpret_cast<const float4*>(bias + o4);
            float4 a = *reinterpret_cast<const float4*>(addm + (size_t)rr * 128 + o4);
            res.x = a.x + id * (res.x + c * (q.x + b.x));
            res.y = a.y + id * (res.y + c * (q.y + b.y));
            res.z = a.z + id * (res.z + c * (q.z + b.z));
            res.w = a.w + id * (res.w + c * (q.w + b.w));
        }
        *reinterpret_cast<float4*>(Y + (size_t)rr * 128 + o4) = res;
    }
}

// wrappers bind device-global scratch (host can't take their addresses)
__global__ void gemm_Q_kernel(const float* efeat, const float* p1W) {
    gemm_body<0>(efeat, p1W, 256, 128, g_Q, NE, nullptr, nullptr, nullptr, nullptr, nullptr);
}
__global__ void gemm_Q2_kernel(const float* efeat, const float* p2W) {
    gemm_body<0>(efeat, p2W, 256, 128, g_Q2, NE, nullptr, nullptr, nullptr, nullptr, nullptr);
}
__global__ void gemm_A_kernel(const float* p1W, const float* p1b) {
    gemm_body<1>(g_Tv, p1W, 256, 0, g_A, NE, g_Q, g_S1, nullptr, p1b, nullptr);
}
__global__ void gemm_vout_kernel(const float* Wv, float* vout) {
    gemm_body<2>(g_vf, Wv, 128, 0, vout, NN, nullptr, nullptr, nullptr, nullptr, nullptr);
}
__global__ void gemm_B_kernel(const float* p2W, const float* p2b, const float* invDE) {
    gemm_body<3>(g_T2, p2W, 256, 0, g_M, NE, g_Q2, g_cnt, invDE, p2b, g_ef2);
}
__global__ void gemm_eout_kernel(const float* We, float* eout) {
    gemm_body<2>(g_M, We, 128, 0, eout, NE, nullptr, nullptr, nullptr, nullptr, nullptr);
}

// ---------------- launcher ----------------
extern "C" void kernel_launch(void* const* d_in, const int* in_sizes, int n_in,
                              void* d_out, int out_size) {
    const float* vfeat  = (const float*)d_in[0];
    const float* efeat  = (const float*)d_in[1];
    const float* invDV  = (const float*)d_in[2];
    const float* invDE  = (const float*)d_in[3];
    const int*   inc_src = (const int*)d_in[4];
    const int*   inc_dst = (const int*)d_in[5];
    const int*   em_r   = (const int*)d_in[6];
    const int*   em_c   = (const int*)d_in[7];
    const float* em_v   = (const float*)d_in[8];
    const int*   vm_r   = (const int*)d_in[9];
    const int*   vm_c   = (const int*)d_in[10];
    const float* vm_v   = (const float*)d_in[11];
    const float* Wv     = (const float*)d_in[12];
    const float* We     = (const float*)d_in[13];
    const float* p1W    = (const float*)d_in[14];
    const float* p1b    = (const float*)d_in[15];
    const float* p2W    = (const float*)d_in[16];
    const float* p2b    = (const float*)d_in[17];

    float* out  = (float*)d_out;
    float* vout = out;                       // [NN, 128]
    float* eout = out + (size_t)NN * D;      // [NE, 128]

    const int TB = 256;
    int grid_init = (NN * D + TB - 1) / TB;          // 25000
    int grid_inc  = (NNZ_INC * 32 + TB - 1) / TB;    // 50000 (warp per nnz)
    int grid_eme  = (NNZ_E * 32 + TB - 1) / TB;      // 10000
    int grid_vme  = (NNZ_V * 32 + TB - 1) / TB;      // 50000
    int grid_gE   = (NE + 31) / 32;                  // 313
    int grid_gN   = (NN + 31) / 32;                  // 1563

    init_kernel<<<grid_init, TB>>>(efeat);
    gemm_Q_kernel<<<grid_gE, TB>>>(efeat, p1W);
    gemm_Q2_kernel<<<grid_gE, TB>>>(efeat, p2W);
    pass1_kernel<<<grid_inc, TB>>>(inc_src, inc_dst, vfeat, efeat, invDV);
    gemm_A_kernel<<<grid_gE, TB>>>(p1W, p1b);
    spmm_e_kernel<<<grid_eme, TB>>>(em_r, em_c, em_v);
    spmm_v_kernel<<<grid_vme, TB>>>(vm_r, vm_c, vm_v);
    pass2_kernel<<<grid_inc, TB>>>(inc_src, inc_dst);
    gemm_vout_kernel<<<grid_gN, TB>>>(Wv, vout);
    pass3_kernel<<<grid_inc, TB>>>(inc_src, inc_dst, vout);
    gemm_B_kernel<<<grid_gE, TB>>>(p2W, p2b, invDE);
    gemm_eout_kernel<<<grid_gE, TB>>>(We, eout);
}

// round 9
// speedup vs baseline: 1.1194x; 1.1194x over previous
#include <cuda_runtime.h>

#define NN 50000
#define NE 10000
#define D  128
#define NNZ_INC 400000
#define NNZ_E   80000
#define NNZ_V   400000

// ---------------- scratch (device globals; no allocation allowed) ----------------
__device__ __align__(128) float g_Tv[NE * D];    // sum invDV[s]*vfeat[s] per edge
__device__ __align__(128) float g_Q[NE * D];     // efeat @ W1e.T
__device__ __align__(128) float g_Q2[NE * D];    // efeat @ W2e.T
__device__ __align__(128) float g_S1[NE];        // sum invDV[s] per edge
__device__ __align__(128) float g_cnt[NE];       // incidence count per edge (float)
__device__ __align__(128) float g_A[NE * D];     // pre-spmm A
__device__ __align__(128) float g_ef1[NE * D];   // _efeat = efeat + emat@A
__device__ __align__(128) float g_T2[NE * D];    // sum vout[s] per edge
__device__ __align__(128) float g_ef2[NE * D];   // sum _vfeat2m[s] per edge
__device__ __align__(128) float g_M[NE * D];     // _efeat2 + B
__device__ __align__(128) float g_vf[NN * D];    // _vfeat
__device__ __align__(128) float g_vf2[NN * D];   // _vfeat2 (pre-spmm)
__device__ __align__(128) float g_vf2m[NN * D];  // vmat @ _vfeat2

// ---------------- CSR structures (built on device each launch) ----------------
__device__ int g_eCnt[NE], g_ePtr[NE + 1], g_eCur[NE];      // incidence by dst (edge)
__device__ int g_vCnt[NN], g_vPtr[NN + 1], g_vCur[NN];      // incidence by src (node)
__device__ int g_emCnt[NE], g_emPtr[NE + 1], g_emCur[NE];   // emat by row
__device__ int g_vmCnt[NN], g_vmPtr[NN + 1], g_vmCur[NN];   // vmat by row
__device__ int   g_eIdx[NNZ_INC];    // src node per edge-CSR slot
__device__ int   g_vIdx[NNZ_INC];    // dst edge per node-CSR slot
__device__ int   g_emCol[NNZ_E];
__device__ float g_emVal[NNZ_E];
__device__ int   g_vmCol[NNZ_V];
__device__ float g_vmVal[NNZ_V];

// ---------------- build step 1: zero counters ----------------
__global__ void zero_counters() {
    int t = blockIdx.x * 256 + threadIdx.x;
    if (t < NE) { g_eCnt[t] = 0; g_emCnt[t] = 0; }
    if (t < NN) { g_vCnt[t] = 0; g_vmCnt[t] = 0; }
}

// ---------------- build step 2: fused histograms ----------------
__global__ void hist_kernel(const int* __restrict__ src, const int* __restrict__ dst,
                            const int* __restrict__ em_r, const int* __restrict__ vm_r) {
    int i = blockIdx.x * 256 + threadIdx.x;
    if (i < NNZ_INC) {
        atomicAdd(g_eCnt + dst[i], 1);
        atomicAdd(g_vCnt + src[i], 1);
        atomicAdd(g_vmCnt + vm_r[i], 1);
    }
    if (i < NNZ_E) atomicAdd(g_emCnt + em_r[i], 1);
}

// ---------------- build step 3: exclusive scan (one block per array) ----------------
__device__ void scan_impl(const int* __restrict__ cnt, int* __restrict__ ptr,
                          int* __restrict__ cur, int n) {
    __shared__ int part[1024];
    int t = threadIdx.x;
    int chunk = (n + 1023) >> 10;
    int lo = t * chunk, hi = min(lo + chunk, n);
    int s = 0;
    for (int i = lo; i < hi; i++) s += cnt[i];
    part[t] = s;
    __syncthreads();
    for (int off = 1; off < 1024; off <<= 1) {
        int mine = part[t];
        int add = (t >= off) ? part[t - off] : 0;
        __syncthreads();
        part[t] = mine + add;
        __syncthreads();
    }
    int run = (t > 0) ? part[t - 1] : 0;
    for (int i = lo; i < hi; i++) { ptr[i] = run; cur[i] = run; run += cnt[i]; }
    if (t == 1023) ptr[n] = part[1023];
}

__global__ void scan_kernel() {
    switch (blockIdx.x) {
        case 0: scan_impl(g_eCnt,  g_ePtr,  g_eCur,  NE); break;
        case 1: scan_impl(g_vCnt,  g_vPtr,  g_vCur,  NN); break;
        case 2: scan_impl(g_emCnt, g_emPtr, g_emCur, NE); break;
        case 3: scan_impl(g_vmCnt, g_vmPtr, g_vmCur, NN); break;
    }
}

// ---------------- build step 4: fused binning ----------------
__global__ void bin_kernel(const int* __restrict__ src, const int* __restrict__ dst,
                           const int* __restrict__ em_r, const int* __restrict__ em_c,
                           const float* __restrict__ em_v,
                           const int* __restrict__ vm_r, const int* __restrict__ vm_c,
                           const float* __restrict__ vm_v) {
    int i = blockIdx.x * 256 + threadIdx.x;
    if (i < NNZ_INC) {
        int s = src[i], e = dst[i];
        int p0 = atomicAdd(g_eCur + e, 1);
        g_eIdx[p0] = s;
        int p1 = atomicAdd(g_vCur + s, 1);
        g_vIdx[p1] = e;
        int p3 = atomicAdd(g_vmCur + vm_r[i], 1);
        g_vmCol[p3] = vm_c[i];
        g_vmVal[p3] = vm_v[i];
    }
    if (i < NNZ_E) {
        int p2 = atomicAdd(g_emCur + em_r[i], 1);
        g_emCol[p2] = em_c[i];
        g_emVal[p2] = em_v[i];
    }
}

// ---------------- gather pass: Tv[e] = sum w*vfeat[s]; S1, cnt ----------------
__global__ void edge_pass1(const float* __restrict__ vfeat, const float* __restrict__ invDV) {
    int e = (blockIdx.x * blockDim.x + threadIdx.x) >> 5;
    if (e >= NE) return;
    int lane = threadIdx.x & 31;
    int b = g_ePtr[e], t = g_ePtr[e + 1];
    float4 acc = make_float4(0.f, 0.f, 0.f, 0.f);
    float ssum = 0.f;
    int j = b;
    for (; j + 1 < t; j += 2) {
        int s0 = g_eIdx[j], s1 = g_eIdx[j + 1];
        float w0 = __ldg(invDV + s0), w1 = __ldg(invDV + s1);
        float4 v0 = __ldg(reinterpret_cast<const float4*>(vfeat + (size_t)s0 * D) + lane);
        float4 v1 = __ldg(reinterpret_cast<const float4*>(vfeat + (size_t)s1 * D) + lane);
        acc.x += w0 * v0.x + w1 * v1.x;
        acc.y += w0 * v0.y + w1 * v1.y;
        acc.z += w0 * v0.z + w1 * v1.z;
        acc.w += w0 * v0.w + w1 * v1.w;
        ssum += w0 + w1;
    }
    if (j < t) {
        int s0 = g_eIdx[j];
        float w0 = __ldg(invDV + s0);
        float4 v0 = __ldg(reinterpret_cast<const float4*>(vfeat + (size_t)s0 * D) + lane);
        acc.x += w0 * v0.x; acc.y += w0 * v0.y; acc.z += w0 * v0.z; acc.w += w0 * v0.w;
        ssum += w0;
    }
    reinterpret_cast<float4*>(g_Tv + (size_t)e * D)[lane] = acc;
    if (lane == 0) { g_S1[e] = ssum; g_cnt[e] = (float)(t - b); }
}

// ---------------- gather body: Y[node] = sum X[edge] over node's incidences -------
__device__ __forceinline__ void node_gather_body(const float* __restrict__ X,
                                                 float* __restrict__ Y) {
    int s = (blockIdx.x * blockDim.x + threadIdx.x) >> 5;
    if (s >= NN) return;
    int lane = threadIdx.x & 31;
    int b = g_vPtr[s], t = g_vPtr[s + 1];
    float4 acc = make_float4(0.f, 0.f, 0.f, 0.f);
    int j = b;
    for (; j + 1 < t; j += 2) {
        int e0 = g_vIdx[j], e1 = g_vIdx[j + 1];
        float4 v0 = __ldg(reinterpret_cast<const float4*>(X + (size_t)e0 * D) + lane);
        float4 v1 = __ldg(reinterpret_cast<const float4*>(X + (size_t)e1 * D) + lane);
        acc.x += v0.x + v1.x; acc.y += v0.y + v1.y;
        acc.z += v0.z + v1.z; acc.w += v0.w + v1.w;
    }
    if (j < t) {
        int e0 = g_vIdx[j];
        float4 v0 = __ldg(reinterpret_cast<const float4*>(X + (size_t)e0 * D) + lane);
        acc.x += v0.x; acc.y += v0.y; acc.z += v0.z; acc.w += v0.w;
    }
    reinterpret_cast<float4*>(Y + (size_t)s * D)[lane] = acc;
}

// Wrappers: __device__ globals MUST be bound from device code (host-side symbol
// addresses are shadow addresses — passing them from the launcher silently
// reads/writes host memory under ATS; that was the R8 bug).
__global__ void node_gather_vf2(const float* __restrict__ efeat) {
    node_gather_body(efeat, g_vf2);   // vf2 = seg-sum efeat[e] per node
}
__global__ void node_gather_vf() {
    node_gather_body(g_ef1, g_vf);    // vf = seg-sum ef1[e] per node
}

// ---------------- gather pass 3: T2[e]=sum vout[s]; ef2[e]=sum vf2m[s] ----------
__global__ void edge_pass3(const float* __restrict__ vout) {
    int e = (blockIdx.x * blockDim.x + threadIdx.x) >> 5;
    if (e >= NE) return;
    int lane = threadIdx.x & 31;
    int b = g_ePtr[e], t = g_ePtr[e + 1];
    float4 a1 = make_float4(0.f, 0.f, 0.f, 0.f);
    float4 a2 = make_float4(0.f, 0.f, 0.f, 0.f);
    for (int j = b; j < t; j++) {
        int s = g_eIdx[j];
        float4 u = __ldg(reinterpret_cast<const float4*>(vout + (size_t)s * D) + lane);
        float4 w = __ldg(reinterpret_cast<const float4*>(g_vf2m + (size_t)s * D) + lane);
        a1.x += u.x; a1.y += u.y; a1.z += u.z; a1.w += u.w;
        a2.x += w.x; a2.y += w.y; a2.z += w.z; a2.w += w.w;
    }
    reinterpret_cast<float4*>(g_T2 + (size_t)e * D)[lane] = a1;
    reinterpret_cast<float4*>(g_ef2 + (size_t)e * D)[lane] = a2;
}

// ---------------- CSR SpMM gather: Y[r] = seed(r) + sum val*X[col] ----------------
template <bool SEED>
__device__ __forceinline__ void spmm_gather_body(const int* __restrict__ ptr,
                                                 const int* __restrict__ col,
                                                 const float* __restrict__ val,
                                                 const float* __restrict__ X,
                                                 const float* __restrict__ seed,
                                                 float* __restrict__ Y, int nrows) {
    int r = (blockIdx.x * blockDim.x + threadIdx.x) >> 5;
    if (r >= nrows) return;
    int lane = threadIdx.x & 31;
    int b = ptr[r], t = ptr[r + 1];
    float4 acc;
    if (SEED) acc = __ldg(reinterpret_cast<const float4*>(seed + (size_t)r * D) + lane);
    else      acc = make_float4(0.f, 0.f, 0.f, 0.f);
    int j = b;
    for (; j + 1 < t; j += 2) {
        int c0 = col[j], c1 = col[j + 1];
        float v0 = val[j], v1 = val[j + 1];
        float4 x0 = __ldg(reinterpret_cast<const float4*>(X + (size_t)c0 * D) + lane);
        float4 x1 = __ldg(reinterpret_cast<const float4*>(X + (size_t)c1 * D) + lane);
        acc.x += v0 * x0.x + v1 * x1.x;
        acc.y += v0 * x0.y + v1 * x1.y;
        acc.z += v0 * x0.z + v1 * x1.z;
        acc.w += v0 * x0.w + v1 * x1.w;
    }
    if (j < t) {
        int c0 = col[j];
        float v0 = val[j];
        float4 x0 = __ldg(reinterpret_cast<const float4*>(X + (size_t)c0 * D) + lane);
        acc.x += v0 * x0.x; acc.y += v0 * x0.y; acc.z += v0 * x0.z; acc.w += v0 * x0.w;
    }
    reinterpret_cast<float4*>(Y + (size_t)r * D)[lane] = acc;
}

__global__ void spmm_e_gather(const float* __restrict__ efeat) {
    // ef1 = efeat + emat @ A
    spmm_gather_body<true>(g_emPtr, g_emCol, g_emVal, g_A, efeat, g_ef1, NE);
}
__global__ void spmm_v_gather() {
    // vf2m = vmat @ vf2
    spmm_gather_body<false>(g_vmPtr, g_vmCol, g_vmVal, g_vf2, nullptr, g_vf2m, NN);
}

// ---------------- GEMM: Y = X[rows,128] @ W.T (+ epilogue) ----------------
// W row-major [128, ldw], use columns [koff, koff+128).
// MODE 0: plain     MODE 2: relu
// MODE 1: Y = acc + (P1[r]+bias)*sc1[r]
// MODE 3: Y = addm[r] + sc2[r]*(acc + sc1[r]*(P1[r]+bias))
// NOTE: ws row stride must be a multiple of 4 floats (LDS.128 alignment).
template <int MODE>
__device__ __forceinline__ void gemm_body(const float* __restrict__ X, const float* __restrict__ W,
                                          int ldw, int koff, float* __restrict__ Y, int rows,
                                          const float* __restrict__ P1, const float* __restrict__ sc1,
                                          const float* __restrict__ sc2, const float* __restrict__ bias,
                                          const float* __restrict__ addm) {
    __shared__ float xs[32][128];
    __shared__ __align__(16) float ws[32][132];
    int r0 = blockIdx.x * 32;
    int tid = threadIdx.x;

    for (int idx = tid; idx < 32 * 128; idx += 256) {
        int r = idx >> 7, k = idx & 127;
        int rr = r0 + r;
        xs[r][k] = (rr < rows) ? X[(size_t)rr * 128 + k] : 0.f;
    }

    int lane = tid & 31;
    int rloc = (tid >> 5) * 4;
    int o4 = lane * 4;
    float acc[4][4];
#pragma unroll
    for (int i = 0; i < 4; i++)
#pragma unroll
        for (int j = 0; j < 4; j++) acc[i][j] = 0.f;

    for (int kt = 0; kt < 128; kt += 32) {
        __syncthreads();
        for (int idx = tid; idx < 32 * 128; idx += 256) {
            int o = idx >> 5, kk = idx & 31;
            ws[kk][o] = W[(size_t)o * ldw + koff + kt + kk];
        }
        __syncthreads();
#pragma unroll
        for (int kk = 0; kk < 32; kk++) {
            float4 wv = *reinterpret_cast<const float4*>(&ws[kk][o4]);
#pragma unroll
            for (int i = 0; i < 4; i++) {
                float xv = xs[rloc + i][kt + kk];
                acc[i][0] += xv * wv.x;
                acc[i][1] += xv * wv.y;
                acc[i][2] += xv * wv.z;
                acc[i][3] += xv * wv.w;
            }
        }
    }

#pragma unroll
    for (int i = 0; i < 4; i++) {
        int rr = r0 + rloc + i;
        if (rr >= rows) continue;
        float4 res = make_float4(acc[i][0], acc[i][1], acc[i][2], acc[i][3]);
        if (MODE == 1) {
            float s = sc1[rr];
            float4 q = *reinterpret_cast<const float4*>(P1 + (size_t)rr * 128 + o4);
            float4 b = *reinterpret_cast<const float4*>(bias + o4);
            res.x += (q.x + b.x) * s;
            res.y += (q.y + b.y) * s;
            res.z += (q.z + b.z) * s;
            res.w += (q.w + b.w) * s;
        } else if (MODE == 2) {
            res.x = fmaxf(res.x, 0.f); res.y = fmaxf(res.y, 0.f);
            res.z = fmaxf(res.z, 0.f); res.w = fmaxf(res.w, 0.f);
        } else if (MODE == 3) {
            float c = sc1[rr];
            float id = sc2[rr];
            float4 q = *reinterpret_cast<const float4*>(P1 + (size_t)rr * 128 + o4);
            float4 b = *reinterpret_cast<const float4*>(bias + o4);
            float4 a = *reinterpret_cast<const float4*>(addm + (size_t)rr * 128 + o4);
            res.x = a.x + id * (res.x + c * (q.x + b.x));
            res.y = a.y + id * (res.y + c * (q.y + b.y));
            res.z = a.z + id * (res.z + c * (q.z + b.z));
            res.w = a.w + id * (res.w + c * (q.w + b.w));
        }
        *reinterpret_cast<float4*>(Y + (size_t)rr * 128 + o4) = res;
    }
}

__global__ void gemm_Q_kernel(const float* efeat, const float* p1W) {
    gemm_body<0>(efeat, p1W, 256, 128, g_Q, NE, nullptr, nullptr, nullptr, nullptr, nullptr);
}
__global__ void gemm_Q2_kernel(const float* efeat, const float* p2W) {
    gemm_body<0>(efeat, p2W, 256, 128, g_Q2, NE, nullptr, nullptr, nullptr, nullptr, nullptr);
}
__global__ void gemm_A_kernel(const float* p1W, const float* p1b) {
    gemm_body<1>(g_Tv, p1W, 256, 0, g_A, NE, g_Q, g_S1, nullptr, p1b, nullptr);
}
__global__ void gemm_vout_kernel(const float* Wv, float* vout) {
    gemm_body<2>(g_vf, Wv, 128, 0, vout, NN, nullptr, nullptr, nullptr, nullptr, nullptr);
}
__global__ void gemm_B_kernel(const float* p2W, const float* p2b, const float* invDE) {
    gemm_body<3>(g_T2, p2W, 256, 0, g_M, NE, g_Q2, g_cnt, invDE, p2b, g_ef2);
}
__global__ void gemm_eout_kernel(const float* We, float* eout) {
    gemm_body<2>(g_M, We, 128, 0, eout, NE, nullptr, nullptr, nullptr, nullptr, nullptr);
}

// ---------------- launcher ----------------
extern "C" void kernel_launch(void* const* d_in, const int* in_sizes, int n_in,
                              void* d_out, int out_size) {
    const float* vfeat  = (const float*)d_in[0];
    const float* efeat  = (const float*)d_in[1];
    const float* invDV  = (const float*)d_in[2];
    const float* invDE  = (const float*)d_in[3];
    const int*   inc_src = (const int*)d_in[4];
    const int*   inc_dst = (const int*)d_in[5];
    const int*   em_r   = (const int*)d_in[6];
    const int*   em_c   = (const int*)d_in[7];
    const float* em_v   = (const float*)d_in[8];
    const int*   vm_r   = (const int*)d_in[9];
    const int*   vm_c   = (const int*)d_in[10];
    const float* vm_v   = (const float*)d_in[11];
    const float* Wv     = (const float*)d_in[12];
    const float* We     = (const float*)d_in[13];
    const float* p1W    = (const float*)d_in[14];
    const float* p1b    = (const float*)d_in[15];
    const float* p2W    = (const float*)d_in[16];
    const float* p2b    = (const float*)d_in[17];

    float* out  = (float*)d_out;
    float* vout = out;                       // [NN, 128]
    float* eout = out + (size_t)NN * D;      // [NE, 128]

    const int TB = 256;
    int grid_z    = (NN + TB - 1) / TB;
    int grid_nnz  = (NNZ_INC + TB - 1) / TB;
    int grid_eW   = (NE * 32 + TB - 1) / TB;         // warp per edge
    int grid_nW   = (NN * 32 + TB - 1) / TB;         // warp per node
    int grid_gE   = (NE + 31) / 32;
    int grid_gN   = (NN + 31) / 32;

    // --- CSR build ---
    zero_counters<<<grid_z, TB>>>();
    hist_kernel<<<grid_nnz, TB>>>(inc_src, inc_dst, em_r, vm_r);
    scan_kernel<<<4, 1024>>>();
    bin_kernel<<<grid_nnz, TB>>>(inc_src, inc_dst, em_r, em_c, em_v, vm_r, vm_c, vm_v);

    // --- main pipeline (all gathers, no fp atomics) ---
    gemm_Q_kernel<<<grid_gE, TB>>>(efeat, p1W);
    gemm_Q2_kernel<<<grid_gE, TB>>>(efeat, p2W);
    edge_pass1<<<grid_eW, TB>>>(vfeat, invDV);
    gemm_A_kernel<<<grid_gE, TB>>>(p1W, p1b);
    spmm_e_gather<<<grid_eW, TB>>>(efeat);           // ef1 = efeat + emat@A
    node_gather_vf2<<<grid_nW, TB>>>(efeat);         // vf2 = seg-sum efeat[e]
    spmm_v_gather<<<grid_nW, TB>>>();                // vf2m = vmat@vf2
    node_gather_vf<<<grid_nW, TB>>>();               // vf  = seg-sum ef1[e]
    gemm_vout_kernel<<<grid_gN, TB>>>(Wv, vout);
    edge_pass3<<<grid_eW, TB>>>(vout);               // T2, ef2
    gemm_B_kernel<<<grid_gE, TB>>>(p2W, p2b, invDE);
    gemm_eout_kernel<<<grid_gE, TB>>>(We, eout);
}

// round 10
// speedup vs baseline: 1.1641x; 1.0399x over previous
#include <cuda_runtime.h>

#define NN 50000
#define NE 10000
#define D  128
#define NNZ_INC 400000
#define NNZ_E   80000
#define NNZ_V   400000

// ---------------- scratch (device globals; no allocation allowed) ----------------
__device__ __align__(128) float g_Tv[NE * D];    // sum invDV[s]*vfeat[s] per edge
__device__ __align__(128) float g_Q[NE * D];     // efeat @ W1e.T
__device__ __align__(128) float g_Q2[NE * D];    // efeat @ W2e.T
__device__ __align__(128) float g_S1[NE];        // sum invDV[s] per edge
__device__ __align__(128) float g_cnt[NE];       // incidence count per edge (float)
__device__ __align__(128) float g_A[NE * D];     // pre-spmm A
__device__ __align__(128) float g_ef1[NE * D];   // _efeat = efeat + emat@A
__device__ __align__(128) float g_T2[NE * D];    // sum vout[s] per edge
__device__ __align__(128) float g_ef2[NE * D];   // sum _vfeat2m[s] per edge
__device__ __align__(128) float g_M[NE * D];     // _efeat2 + B
__device__ __align__(128) float g_vf[NN * D];    // _vfeat
__device__ __align__(128) float g_vf2[NN * D];   // _vfeat2 (pre-spmm)
__device__ __align__(128) float g_vf2m[NN * D];  // vmat @ _vfeat2

// ---------------- CSR structures (built on device each launch) ----------------
__device__ int g_eCnt[NE], g_ePtr[NE + 1], g_eCur[NE];      // incidence by dst (edge)
__device__ int g_vCnt[NN], g_vPtr[NN + 1], g_vCur[NN];      // incidence by src (node)
__device__ int g_emCnt[NE], g_emPtr[NE + 1], g_emCur[NE];   // emat by row
__device__ int g_vmCnt[NN], g_vmPtr[NN + 1], g_vmCur[NN];   // vmat by row
__device__ int   g_eIdx[NNZ_INC];    // src node per edge-CSR slot
__device__ int   g_vIdx[NNZ_INC];    // dst edge per node-CSR slot
__device__ int   g_emCol[NNZ_E];
__device__ float g_emVal[NNZ_E];
__device__ int   g_vmCol[NNZ_V];
__device__ float g_vmVal[NNZ_V];

// ---------------- build step 1: zero counters ----------------
__global__ void zero_counters() {
    int t = blockIdx.x * 256 + threadIdx.x;
    if (t < NE) { g_eCnt[t] = 0; g_emCnt[t] = 0; }
    if (t < NN) { g_vCnt[t] = 0; g_vmCnt[t] = 0; }
}

// ---------------- build step 2: fused histograms ----------------
__global__ void hist_kernel(const int* __restrict__ src, const int* __restrict__ dst,
                            const int* __restrict__ em_r, const int* __restrict__ vm_r) {
    int i = blockIdx.x * 256 + threadIdx.x;
    if (i < NNZ_INC) {
        atomicAdd(g_eCnt + dst[i], 1);
        atomicAdd(g_vCnt + src[i], 1);
        atomicAdd(g_vmCnt + vm_r[i], 1);
    }
    if (i < NNZ_E) atomicAdd(g_emCnt + em_r[i], 1);
}

// ---------------- build step 3: exclusive scan (one block per array) ----------------
__device__ void scan_impl(const int* __restrict__ cnt, int* __restrict__ ptr,
                          int* __restrict__ cur, int n) {
    __shared__ int part[1024];
    int t = threadIdx.x;
    int chunk = (n + 1023) >> 10;
    int lo = t * chunk, hi = min(lo + chunk, n);
    int s = 0;
    for (int i = lo; i < hi; i++) s += cnt[i];
    part[t] = s;
    __syncthreads();
    for (int off = 1; off < 1024; off <<= 1) {
        int mine = part[t];
        int add = (t >= off) ? part[t - off] : 0;
        __syncthreads();
        part[t] = mine + add;
        __syncthreads();
    }
    int run = (t > 0) ? part[t - 1] : 0;
    for (int i = lo; i < hi; i++) { ptr[i] = run; cur[i] = run; run += cnt[i]; }
    if (t == 1023) ptr[n] = part[1023];
}

__global__ void scan_kernel() {
    switch (blockIdx.x) {
        case 0: scan_impl(g_eCnt,  g_ePtr,  g_eCur,  NE); break;
        case 1: scan_impl(g_vCnt,  g_vPtr,  g_vCur,  NN); break;
        case 2: scan_impl(g_emCnt, g_emPtr, g_emCur, NE); break;
        case 3: scan_impl(g_vmCnt, g_vmPtr, g_vmCur, NN); break;
    }
}

// ---------------- build step 4: fused binning ----------------
__global__ void bin_kernel(const int* __restrict__ src, const int* __restrict__ dst,
                           const int* __restrict__ em_r, const int* __restrict__ em_c,
                           const float* __restrict__ em_v,
                           const int* __restrict__ vm_r, const int* __restrict__ vm_c,
                           const float* __restrict__ vm_v) {
    int i = blockIdx.x * 256 + threadIdx.x;
    if (i < NNZ_INC) {
        int s = src[i], e = dst[i];
        int p0 = atomicAdd(g_eCur + e, 1);
        g_eIdx[p0] = s;
        int p1 = atomicAdd(g_vCur + s, 1);
        g_vIdx[p1] = e;
        int p3 = atomicAdd(g_vmCur + vm_r[i], 1);
        g_vmCol[p3] = vm_c[i];
        g_vmVal[p3] = vm_v[i];
    }
    if (i < NNZ_E) {
        int p2 = atomicAdd(g_emCur + em_r[i], 1);
        g_emCol[p2] = em_c[i];
        g_emVal[p2] = em_v[i];
    }
}

// ---------------- gather pass: Tv[e] = sum w*vfeat[s]; S1, cnt ----------------
__global__ void edge_pass1(const float* __restrict__ vfeat, const float* __restrict__ invDV) {
    int e = (blockIdx.x * blockDim.x + threadIdx.x) >> 5;
    if (e >= NE) return;
    int lane = threadIdx.x & 31;
    int b = g_ePtr[e], t = g_ePtr[e + 1];
    float4 acc = make_float4(0.f, 0.f, 0.f, 0.f);
    float ssum = 0.f;
    int j = b;
    for (; j + 1 < t; j += 2) {
        int s0 = g_eIdx[j], s1 = g_eIdx[j + 1];
        float w0 = __ldg(invDV + s0), w1 = __ldg(invDV + s1);
        float4 v0 = __ldg(reinterpret_cast<const float4*>(vfeat + (size_t)s0 * D) + lane);
        float4 v1 = __ldg(reinterpret_cast<const float4*>(vfeat + (size_t)s1 * D) + lane);
        acc.x += w0 * v0.x + w1 * v1.x;
        acc.y += w0 * v0.y + w1 * v1.y;
        acc.z += w0 * v0.z + w1 * v1.z;
        acc.w += w0 * v0.w + w1 * v1.w;
        ssum += w0 + w1;
    }
    if (j < t) {
        int s0 = g_eIdx[j];
        float w0 = __ldg(invDV + s0);
        float4 v0 = __ldg(reinterpret_cast<const float4*>(vfeat + (size_t)s0 * D) + lane);
        acc.x += w0 * v0.x; acc.y += w0 * v0.y; acc.z += w0 * v0.z; acc.w += w0 * v0.w;
        ssum += w0;
    }
    reinterpret_cast<float4*>(g_Tv + (size_t)e * D)[lane] = acc;
    if (lane == 0) { g_S1[e] = ssum; g_cnt[e] = (float)(t - b); }
}

// ---------------- gather body: Y[node] = sum X[edge] over node's incidences -------
__device__ __forceinline__ void node_gather_body(const float* __restrict__ X,
                                                 float* __restrict__ Y) {
    int s = (blockIdx.x * blockDim.x + threadIdx.x) >> 5;
    if (s >= NN) return;
    int lane = threadIdx.x & 31;
    int b = g_vPtr[s], t = g_vPtr[s + 1];
    float4 acc = make_float4(0.f, 0.f, 0.f, 0.f);
    int j = b;
    for (; j + 1 < t; j += 2) {
        int e0 = g_vIdx[j], e1 = g_vIdx[j + 1];
        float4 v0 = __ldg(reinterpret_cast<const float4*>(X + (size_t)e0 * D) + lane);
        float4 v1 = __ldg(reinterpret_cast<const float4*>(X + (size_t)e1 * D) + lane);
        acc.x += v0.x + v1.x; acc.y += v0.y + v1.y;
        acc.z += v0.z + v1.z; acc.w += v0.w + v1.w;
    }
    if (j < t) {
        int e0 = g_vIdx[j];
        float4 v0 = __ldg(reinterpret_cast<const float4*>(X + (size_t)e0 * D) + lane);
        acc.x += v0.x; acc.y += v0.y; acc.z += v0.z; acc.w += v0.w;
    }
    reinterpret_cast<float4*>(Y + (size_t)s * D)[lane] = acc;
}

// Wrappers: __device__ globals MUST be bound from device code (host-side symbol
// addresses are shadow addresses under ATS — R8 bug).
__global__ void node_gather_vf2(const float* __restrict__ efeat) {
    node_gather_body(efeat, g_vf2);   // vf2 = seg-sum efeat[e] per node
}
__global__ void node_gather_vf() {
    node_gather_body(g_ef1, g_vf);    // vf = seg-sum ef1[e] per node
}

// ---------------- gather pass 3: T2[e]=sum vout[s]; ef2[e]=sum vf2m[s] ----------
__global__ void edge_pass3(const float* __restrict__ vout) {
    int e = (blockIdx.x * blockDim.x + threadIdx.x) >> 5;
    if (e >= NE) return;
    int lane = threadIdx.x & 31;
    int b = g_ePtr[e], t = g_ePtr[e + 1];
    float4 a1 = make_float4(0.f, 0.f, 0.f, 0.f);
    float4 a2 = make_float4(0.f, 0.f, 0.f, 0.f);
    int j = b;
    for (; j + 1 < t; j += 2) {
        int s0 = g_eIdx[j], s1 = g_eIdx[j + 1];
        float4 u0 = __ldg(reinterpret_cast<const float4*>(vout + (size_t)s0 * D) + lane);
        float4 w0 = __ldg(reinterpret_cast<const float4*>(g_vf2m + (size_t)s0 * D) + lane);
        float4 u1 = __ldg(reinterpret_cast<const float4*>(vout + (size_t)s1 * D) + lane);
        float4 w1 = __ldg(reinterpret_cast<const float4*>(g_vf2m + (size_t)s1 * D) + lane);
        a1.x += u0.x + u1.x; a1.y += u0.y + u1.y; a1.z += u0.z + u1.z; a1.w += u0.w + u1.w;
        a2.x += w0.x + w1.x; a2.y += w0.y + w1.y; a2.z += w0.z + w1.z; a2.w += w0.w + w1.w;
    }
    if (j < t) {
        int s0 = g_eIdx[j];
        float4 u0 = __ldg(reinterpret_cast<const float4*>(vout + (size_t)s0 * D) + lane);
        float4 w0 = __ldg(reinterpret_cast<const float4*>(g_vf2m + (size_t)s0 * D) + lane);
        a1.x += u0.x; a1.y += u0.y; a1.z += u0.z; a1.w += u0.w;
        a2.x += w0.x; a2.y += w0.y; a2.z += w0.z; a2.w += w0.w;
    }
    reinterpret_cast<float4*>(g_T2 + (size_t)e * D)[lane] = a1;
    reinterpret_cast<float4*>(g_ef2 + (size_t)e * D)[lane] = a2;
}

// ---------------- CSR SpMM gather: Y[r] = seed(r) + sum val*X[col] ----------------
template <bool SEED>
__device__ __forceinline__ void spmm_gather_body(const int* __restrict__ ptr,
                                                 const int* __restrict__ col,
                                                 const float* __restrict__ val,
                                                 const float* __restrict__ X,
                                                 const float* __restrict__ seed,
                                                 float* __restrict__ Y, int nrows) {
    int r = (blockIdx.x * blockDim.x + threadIdx.x) >> 5;
    if (r >= nrows) return;
    int lane = threadIdx.x & 31;
    int b = ptr[r], t = ptr[r + 1];
    float4 acc;
    if (SEED) acc = __ldg(reinterpret_cast<const float4*>(seed + (size_t)r * D) + lane);
    else      acc = make_float4(0.f, 0.f, 0.f, 0.f);
    int j = b;
    for (; j + 1 < t; j += 2) {
        int c0 = col[j], c1 = col[j + 1];
        float v0 = val[j], v1 = val[j + 1];
        float4 x0 = __ldg(reinterpret_cast<const float4*>(X + (size_t)c0 * D) + lane);
        float4 x1 = __ldg(reinterpret_cast<const float4*>(X + (size_t)c1 * D) + lane);
        acc.x += v0 * x0.x + v1 * x1.x;
        acc.y += v0 * x0.y + v1 * x1.y;
        acc.z += v0 * x0.z + v1 * x1.z;
        acc.w += v0 * x0.w + v1 * x1.w;
    }
    if (j < t) {
        int c0 = col[j];
        float v0 = val[j];
        float4 x0 = __ldg(reinterpret_cast<const float4*>(X + (size_t)c0 * D) + lane);
        acc.x += v0 * x0.x; acc.y += v0 * x0.y; acc.z += v0 * x0.z; acc.w += v0 * x0.w;
    }
    reinterpret_cast<float4*>(Y + (size_t)r * D)[lane] = acc;
}

__global__ void spmm_e_gather(const float* __restrict__ efeat) {
    // ef1 = efeat + emat @ A
    spmm_gather_body<true>(g_emPtr, g_emCol, g_emVal, g_A, efeat, g_ef1, NE);
}
__global__ void spmm_v_gather() {
    // vf2m = vmat @ vf2
    spmm_gather_body<false>(g_vmPtr, g_vmCol, g_vmVal, g_vf2, nullptr, g_vf2m, NN);
}

// ---------------- GEMM: Y = X[rows,128] @ W.T (+ epilogue) ----------------
// W row-major [128, ldw], use columns [koff, koff+128).
// MODE 0: plain     MODE 2: relu
// MODE 1: Y = acc + (P1[r]+bias)*sc1[r]
// MODE 3: Y = addm[r] + sc2[r]*(acc + sc1[r]*(P1[r]+bias))
// NOTE: ws row stride must be a multiple of 4 floats (LDS.128 alignment).
template <int MODE>
__device__ __forceinline__ void gemm_body(const float* __restrict__ X, const float* __restrict__ W,
                                          int ldw, int koff, float* __restrict__ Y, int rows,
                                          const float* __restrict__ P1, const float* __restrict__ sc1,
                                          const float* __restrict__ sc2, const float* __restrict__ bias,
                                          const float* __restrict__ addm) {
    __shared__ float xs[32][128];
    __shared__ __align__(16) float ws[32][132];
    int r0 = blockIdx.x * 32;
    int tid = threadIdx.x;

    for (int idx = tid; idx < 32 * 128; idx += 256) {
        int r = idx >> 7, k = idx & 127;
        int rr = r0 + r;
        xs[r][k] = (rr < rows) ? X[(size_t)rr * 128 + k] : 0.f;
    }

    int lane = tid & 31;
    int rloc = (tid >> 5) * 4;
    int o4 = lane * 4;
    float acc[4][4];
#pragma unroll
    for (int i = 0; i < 4; i++)
#pragma unroll
        for (int j = 0; j < 4; j++) acc[i][j] = 0.f;

    for (int kt = 0; kt < 128; kt += 32) {
        __syncthreads();
        for (int idx = tid; idx < 32 * 128; idx += 256) {
            int o = idx >> 5, kk = idx & 31;
            ws[kk][o] = W[(size_t)o * ldw + koff + kt + kk];
        }
        __syncthreads();
#pragma unroll
        for (int kk = 0; kk < 32; kk++) {
            float4 wv = *reinterpret_cast<const float4*>(&ws[kk][o4]);
#pragma unroll
            for (int i = 0; i < 4; i++) {
                float xv = xs[rloc + i][kt + kk];
                acc[i][0] += xv * wv.x;
                acc[i][1] += xv * wv.y;
                acc[i][2] += xv * wv.z;
                acc[i][3] += xv * wv.w;
            }
        }
    }

#pragma unroll
    for (int i = 0; i < 4; i++) {
        int rr = r0 + rloc + i;
        if (rr >= rows) continue;
        float4 res = make_float4(acc[i][0], acc[i][1], acc[i][2], acc[i][3]);
        if (MODE == 1) {
            float s = sc1[rr];
            float4 q = *reinterpret_cast<const float4*>(P1 + (size_t)rr * 128 + o4);
            float4 b = *reinterpret_cast<const float4*>(bias + o4);
            res.x += (q.x + b.x) * s;
            res.y += (q.y + b.y) * s;
            res.z += (q.z + b.z) * s;
            res.w += (q.w + b.w) * s;
        } else if (MODE == 2) {
            res.x = fmaxf(res.x, 0.f); res.y = fmaxf(res.y, 0.f);
            res.z = fmaxf(res.z, 0.f); res.w = fmaxf(res.w, 0.f);
        } else if (MODE == 3) {
            float c = sc1[rr];
            float id = sc2[rr];
            float4 q = *reinterpret_cast<const float4*>(P1 + (size_t)rr * 128 + o4);
            float4 b = *reinterpret_cast<const float4*>(bias + o4);
            float4 a = *reinterpret_cast<const float4*>(addm + (size_t)rr * 128 + o4);
            res.x = a.x + id * (res.x + c * (q.x + b.x));
            res.y = a.y + id * (res.y + c * (q.y + b.y));
            res.z = a.z + id * (res.z + c * (q.z + b.z));
            res.w = a.w + id * (res.w + c * (q.w + b.w));
        }
        *reinterpret_cast<float4*>(Y + (size_t)rr * 128 + o4) = res;
    }
}

// ---- fused Q/Q2 GEMM: shares the xs tile across both weight matrices ----
__global__ void gemm_QQ2_kernel(const float* __restrict__ efeat,
                                const float* __restrict__ p1W,
                                const float* __restrict__ p2W) {
    __shared__ float xs[32][128];
    __shared__ __align__(16) float ws[32][132];
    int r0 = blockIdx.x * 32;
    int tid = threadIdx.x;

    for (int idx = tid; idx < 32 * 128; idx += 256) {
        int r = idx >> 7, k = idx & 127;
        int rr = r0 + r;
        xs[r][k] = (rr < NE) ? efeat[(size_t)rr * 128 + k] : 0.f;
    }

    int lane = tid & 31;
    int rloc = (tid >> 5) * 4;
    int o4 = lane * 4;

#pragma unroll
    for (int w = 0; w < 2; w++) {
        const float* W = w ? p2W : p1W;
        float* Y = w ? g_Q2 : g_Q;
        float acc[4][4];
#pragma unroll
        for (int i = 0; i < 4; i++)
#pragma unroll
            for (int j = 0; j < 4; j++) acc[i][j] = 0.f;

        for (int kt = 0; kt < 128; kt += 32) {
            __syncthreads();
            for (int idx = tid; idx < 32 * 128; idx += 256) {
                int o = idx >> 5, kk = idx & 31;
                ws[kk][o] = W[(size_t)o * 256 + 128 + kt + kk];
            }
            __syncthreads();
#pragma unroll
            for (int kk = 0; kk < 32; kk++) {
                float4 wv = *reinterpret_cast<const float4*>(&ws[kk][o4]);
#pragma unroll
                for (int i = 0; i < 4; i++) {
                    float xv = xs[rloc + i][kt + kk];
                    acc[i][0] += xv * wv.x;
                    acc[i][1] += xv * wv.y;
                    acc[i][2] += xv * wv.z;
                    acc[i][3] += xv * wv.w;
                }
            }
        }
#pragma unroll
        for (int i = 0; i < 4; i++) {
            int rr = r0 + rloc + i;
            if (rr < NE)
                *reinterpret_cast<float4*>(Y + (size_t)rr * 128 + o4) =
                    make_float4(acc[i][0], acc[i][1], acc[i][2], acc[i][3]);
        }
    }
}

__global__ void gemm_A_kernel(const float* p1W, const float* p1b) {
    gemm_body<1>(g_Tv, p1W, 256, 0, g_A, NE, g_Q, g_S1, nullptr, p1b, nullptr);
}
__global__ void gemm_vout_kernel(const float* Wv, float* vout) {
    gemm_body<2>(g_vf, Wv, 128, 0, vout, NN, nullptr, nullptr, nullptr, nullptr, nullptr);
}
__global__ void gemm_B_kernel(const float* p2W, const float* p2b, const float* invDE) {
    gemm_body<3>(g_T2, p2W, 256, 0, g_M, NE, g_Q2, g_cnt, invDE, p2b, g_ef2);
}
__global__ void gemm_eout_kernel(const float* We, float* eout) {
    gemm_body<2>(g_M, We, 128, 0, eout, NE, nullptr, nullptr, nullptr, nullptr, nullptr);
}

// ---------------- launcher (two-stream fork/join, graph-capturable) ----------------
extern "C" void kernel_launch(void* const* d_in, const int* in_sizes, int n_in,
                              void* d_out, int out_size) {
    const float* vfeat  = (const float*)d_in[0];
    const float* efeat  = (const float*)d_in[1];
    const float* invDV  = (const float*)d_in[2];
    const float* invDE  = (const float*)d_in[3];
    const int*   inc_src = (const int*)d_in[4];
    const int*   inc_dst = (const int*)d_in[5];
    const int*   em_r   = (const int*)d_in[6];
    const int*   em_c   = (const int*)d_in[7];
    const float* em_v   = (const float*)d_in[8];
    const int*   vm_r   = (const int*)d_in[9];
    const int*   vm_c   = (const int*)d_in[10];
    const float* vm_v   = (const float*)d_in[11];
    const float* Wv     = (const float*)d_in[12];
    const float* We     = (const float*)d_in[13];
    const float* p1W    = (const float*)d_in[14];
    const float* p1b    = (const float*)d_in[15];
    const float* p2W    = (const float*)d_in[16];
    const float* p2b    = (const float*)d_in[17];

    float* out  = (float*)d_out;
    float* vout = out;                       // [NN, 128]
    float* eout = out + (size_t)NN * D;      // [NE, 128]

    // one-time infrastructure (no device memory allocated)
    static cudaStream_t s1 = nullptr;
    static cudaEvent_t evFork = nullptr, ev1 = nullptr, ev2 = nullptr;
    if (s1 == nullptr) {
        cudaStreamCreateWithFlags(&s1, cudaStreamNonBlocking);
        cudaEventCreateWithFlags(&evFork, cudaEventDisableTiming);
        cudaEventCreateWithFlags(&ev1, cudaEventDisableTiming);
        cudaEventCreateWithFlags(&ev2, cudaEventDisableTiming);
    }

    const int TB = 256;
    int grid_z    = (NN + TB - 1) / TB;
    int grid_nnz  = (NNZ_INC + TB - 1) / TB;
    int grid_eW   = (NE * 32 + TB - 1) / TB;         // warp per edge
    int grid_nW   = (NN * 32 + TB - 1) / TB;         // warp per node
    int grid_gE   = (NE + 31) / 32;
    int grid_gN   = (NN + 31) / 32;

    // --- CSR build (stream 0) ---
    zero_counters<<<grid_z, TB>>>();
    hist_kernel<<<grid_nnz, TB>>>(inc_src, inc_dst, em_r, vm_r);
    scan_kernel<<<4, 1024>>>();
    bin_kernel<<<grid_nnz, TB>>>(inc_src, inc_dst, em_r, em_c, em_v, vm_r, vm_c, vm_v);

    // --- fork: side stream does the gather-only branch ---
    cudaEventRecord(evFork, 0);
    cudaStreamWaitEvent(s1, evFork, 0);

    edge_pass1<<<grid_eW, TB, 0, s1>>>(vfeat, invDV);          // Tv, S1, cnt
    cudaEventRecord(ev1, s1);
    node_gather_vf2<<<grid_nW, TB, 0, s1>>>(efeat);            // vf2
    spmm_v_gather<<<grid_nW, TB, 0, s1>>>();                   // vf2m = vmat@vf2
    cudaEventRecord(ev2, s1);

    // --- main stream: compute chain, overlapping s1 ---
    gemm_QQ2_kernel<<<grid_gE, TB>>>(efeat, p1W, p2W);         // Q, Q2 (fused)
    cudaStreamWaitEvent(0, ev1, 0);                            // need Tv/S1
    gemm_A_kernel<<<grid_gE, TB>>>(p1W, p1b);                  // A
    spmm_e_gather<<<grid_eW, TB>>>(efeat);                     // ef1 = efeat + emat@A
    node_gather_vf<<<grid_nW, TB>>>();                         // vf
    gemm_vout_kernel<<<grid_gN, TB>>>(Wv, vout);               // vout = relu(vf@Wv.T)
    cudaStreamWaitEvent(0, ev2, 0);                            // need vf2m (join s1)
    edge_pass3<<<grid_eW, TB>>>(vout);                         // T2, ef2
    gemm_B_kernel<<<grid_gE, TB>>>(p2W, p2b, invDE);           // M
    gemm_eout_kernel<<<grid_gE, TB>>>(We, eout);               // eout
}